// round 5
// baseline (speedup 1.0000x reference)
#include <cuda_runtime.h>
#include <math.h>

#define B_SZ 32
#define T_SZ 1024
#define I_SZ 512
#define H_SZ 1024
#define DT_C 0.1f

typedef unsigned long long ull;

// ---------------- f32x2 packed-math helpers (Blackwell FFMA2) -------------
__device__ __forceinline__ ull ffma2(ull a, ull b, ull c) {
    ull d; asm("fma.rn.f32x2 %0, %1, %2, %3;" : "=l"(d) : "l"(a), "l"(b), "l"(c)); return d;
}
__device__ __forceinline__ ull fadd2(ull a, ull b) {
    ull d; asm("add.rn.f32x2 %0, %1, %2;" : "=l"(d) : "l"(a), "l"(b)); return d;
}
__device__ __forceinline__ ull pack2(float lo, float hi) {
    ull d; asm("mov.b64 %0, {%1, %2};" : "=l"(d) : "f"(lo), "f"(hi)); return d;
}
__device__ __forceinline__ float2 unpack2(ull v) {
    float2 r; asm("mov.b64 {%0, %1}, %2;" : "=f"(r.x), "=f"(r.y) : "l"(v)); return r;
}

// ------------------------------------------------------------------
// Persistent-kernel global state
// g_hT: transposed hidden state double buffer: [2][H][B]  (k-major)
// ------------------------------------------------------------------
#define RBLK 128
__device__ float g_hT[2][H_SZ * B_SZ];
__device__ volatile int g_arrive[RBLK];
__device__ volatile int g_release;

__global__ void reset_kernel() {
    int idx = blockIdx.x * blockDim.x + threadIdx.x;
    if (idx < H_SZ * B_SZ) g_hT[0][idx] = 0.0f;
    if (idx < RBLK) g_arrive[idx] = 0;
    if (idx == 0) g_release = 0;
}

// ------------------------------------------------------------------
// xW GEMM: C[M=B*T, H] = X[M, I] @ W[H, I]^T   (fp32, FFMA2 inner)
// 128x64 block tile, BK=16, 256 threads
// ------------------------------------------------------------------
#define GBM 128
#define GBN 64
#define GBK 16

union F4U { float4 f4; ull u[2]; };

__global__ void __launch_bounds__(256) gemm_xw(
    const float* __restrict__ X, const float* __restrict__ W,
    float* __restrict__ C)
{
    __shared__ float Xs[GBK][GBM];
    __shared__ float Ws[GBK][GBN + 4];
    const int tid = threadIdx.x;
    const int tx = tid & 15;   // 16 -> N
    const int ty = tid >> 4;   // 16 -> M
    const int m0 = blockIdx.y * GBM;
    const int n0 = blockIdx.x * GBN;

    ull acc2[4][4];   // [m-pair p][n j]
#pragma unroll
    for (int p = 0; p < 4; p++)
#pragma unroll
        for (int j = 0; j < 4; j++) acc2[p][j] = 0ull;

    for (int k0 = 0; k0 < I_SZ; k0 += GBK) {
#pragma unroll
        for (int pp = 0; pp < 2; pp++) {
            int q = tid + pp * 256;
            int row = q >> 2, qc = q & 3;
            float4 v = *(const float4*)(X + (size_t)(m0 + row) * I_SZ + k0 + qc * 4);
            Xs[qc * 4 + 0][row] = v.x; Xs[qc * 4 + 1][row] = v.y;
            Xs[qc * 4 + 2][row] = v.z; Xs[qc * 4 + 3][row] = v.w;
        }
        {
            int row = tid >> 2, qc = tid & 3;
            float4 v = *(const float4*)(W + (size_t)(n0 + row) * I_SZ + k0 + qc * 4);
            Ws[qc * 4 + 0][row] = v.x; Ws[qc * 4 + 1][row] = v.y;
            Ws[qc * 4 + 2][row] = v.z; Ws[qc * 4 + 3][row] = v.w;
        }
        __syncthreads();
#pragma unroll
        for (int kk = 0; kk < GBK; kk++) {
            F4U a0, a1;
            a0.f4 = *(const float4*)&Xs[kk][ty * 8];
            a1.f4 = *(const float4*)&Xs[kk][ty * 8 + 4];
            float4 bv = *(const float4*)&Ws[kk][tx * 4];
            ull bd[4];
            bd[0] = pack2(bv.x, bv.x); bd[1] = pack2(bv.y, bv.y);
            bd[2] = pack2(bv.z, bv.z); bd[3] = pack2(bv.w, bv.w);
            ull a2[4] = {a0.u[0], a0.u[1], a1.u[0], a1.u[1]};
#pragma unroll
            for (int p = 0; p < 4; p++)
#pragma unroll
                for (int j = 0; j < 4; j++)
                    acc2[p][j] = ffma2(a2[p], bd[j], acc2[p][j]);
        }
        __syncthreads();
    }
#pragma unroll
    for (int p = 0; p < 4; p++) {
        float2 c0 = unpack2(acc2[p][0]);
        float2 c1 = unpack2(acc2[p][1]);
        float2 c2 = unpack2(acc2[p][2]);
        float2 c3 = unpack2(acc2[p][3]);
        float4 lo = make_float4(c0.x, c1.x, c2.x, c3.x);
        float4 hi = make_float4(c0.y, c1.y, c2.y, c3.y);
        *(float4*)(C + (size_t)(m0 + ty * 8 + 2 * p)     * H_SZ + n0 + tx * 4) = lo;
        *(float4*)(C + (size_t)(m0 + ty * 8 + 2 * p + 1) * H_SZ + n0 + tx * 4) = hi;
    }
}

// ------------------------------------------------------------------
// Persistent recurrence kernel.
// grid = 128 blocks (64 j-tiles x 2 b-halves), 512 threads.
// Block tile per step: 16 j x 16 b x 1024 k.
// Thread (tb=tid&1, tj=(tid>>1)&3, ks=tid>>3): 4j x 4 b-pairs x 16k.
// U for k<512 in REGISTERS (u_lo[4][8]); k>=512 in smem Us[16][513].
// h staged k-major: hs[k][16 b], stride 20; staging pipelined in 2 halves.
// ------------------------------------------------------------------
#define JT 16
#define BHALF 16
#define USTR 513                 // 513 % 32 == 1 -> conflict-free u LDS
#define HSTR 20
#define NPO 128
#define RECUR_SMEM ((JT * USTR + H_SZ * HSTR) * 4 + NPO * 64 * 8)

__global__ void __launch_bounds__(512, 1) recur_kernel(
    float* __restrict__ states,      // [B, T, H] (holds xW on entry, states on exit)
    float* __restrict__ hfinal,      // [B, H]
    const float* __restrict__ U,     // [H, H]
    const float* __restrict__ bias,  // [H]
    const float* __restrict__ tau)   // [H]
{
    extern __shared__ float sm[];
    float* Us = sm;                                 // [JT][USTR]  (k in [512,1024))
    float* hs = Us + JT * USTR;                     // [1024][HSTR]
    ull* red = (ull*)(hs + H_SZ * HSTR);            // [NPO][64]

    const int tid = threadIdx.x;
    const int blk = blockIdx.x;
    const int jt = blk & 63;
    const int bh = blk >> 6;
    const int j0 = jt * JT;
    const int bg0 = bh * BHALF;

    const int tb = tid & 1;
    const int tj = (tid >> 1) & 3;
    const int ks = tid >> 3;      // 0..63

    // ---- U slab, upper-k half into smem: Us[row][c] = U[j0+row][512+c] ----
    // Scalar stores only: USTR=513 (odd) makes row*USTR odd for odd rows, so
    // any vector STS would be misaligned (HW trap). Scalar is trap-free.
    for (int q = tid; q < JT * 128; q += 512) {
        int row = q >> 7;
        int c = (q & 127) * 4;
        float4 v = *(const float4*)(U + (size_t)(j0 + row) * H_SZ + 512 + c);
        float* d = Us + row * USTR + c;
        d[0] = v.x; d[1] = v.y; d[2] = v.z; d[3] = v.w;
    }

    // ---- U slab, lower-k half into registers ----
    float u_lo[4][8];
    {
        const float* ub = U + (size_t)(j0 + tj * 4) * H_SZ + ks;
#pragma unroll
        for (int jj = 0; jj < 4; jj++)
#pragma unroll
            for (int kq = 0; kq < 8; kq++)
                u_lo[jj][kq] = __ldg(ub + (size_t)jj * H_SZ + kq * 64);
    }

    // ---- epilogue (reader) setup: tid < 128, sr = tid & 15 ----
    int po = 0, sr = 0, jg = 0, bp = 0;
    float decay = 0.0f, biasj = 0.0f;
    size_t sidx0 = 0, sidx1 = 0;
    float xwA = 0.0f, xwB = 0.0f;
    if (tid < NPO) {
        int r = tid;
        po = ((r >> 1) & 1) | ((r & 1) << 1) | (((r >> 4) & 1) << 2)
           | (((r >> 5) & 1) << 3) | (((r >> 6) & 1) << 4)
           | (((r >> 2) & 1) << 5) | (((r >> 3) & 1) << 6);
        sr = r & 15;
        int j_loc = po >> 3;
        bp = po & 7;
        jg = j0 + j_loc;
        float it = 1.0f / tau[jg];
        decay = 1.0f - DT_C * it;
        biasj = bias[jg];
        int b_glob = bg0 + 2 * bp;
        sidx0 = (size_t)b_glob * T_SZ * H_SZ + jg;
        sidx1 = sidx0 + (size_t)T_SZ * H_SZ;
        xwA = __ldcg(states + sidx0);   // prefetch t = 0
        xwB = __ldcg(states + sidx1);
    }

    int cur = 0;
    __syncthreads();

    for (int t = 0; t < T_SZ; t++) {
        const float* gh = g_hT[cur] + bg0;

        // ---- stage half A: k in [0,512) ----
#pragma unroll
        for (int it4 = 0; it4 < 4; it4++) {
            int q = tid + it4 * 512;
            int k = q >> 2, part = (q & 3) * 4;
            float4 v = __ldcg((const float4*)(gh + (size_t)k * B_SZ + part));
            *(float4*)(hs + k * HSTR + part) = v;   // offset % 4 floats == 0
        }
        __syncthreads();

        // ---- issue loads for half B (latency hides under compute A) ----
        float4 sb[4];
        int kB[4], pB[4];
#pragma unroll
        for (int it4 = 0; it4 < 4; it4++) {
            int q = tid + (it4 + 4) * 512;
            kB[it4] = q >> 2; pB[it4] = (q & 3) * 4;
            sb[it4] = __ldcg((const float4*)(gh + (size_t)kB[it4] * B_SZ + pB[it4]));
        }

        // ---- compute half A: kq 0..7, u from registers ----
        ull acc2[4][4];
#pragma unroll
        for (int jj = 0; jj < 4; jj++)
#pragma unroll
            for (int m = 0; m < 4; m++) acc2[jj][m] = 0ull;

#pragma unroll
        for (int kq = 0; kq < 8; kq++) {
            const float* hrow = hs + (ks + 64 * kq) * HSTR + 2 * tb;
            ull h0 = *(const ull*)(hrow + 0);
            ull h1 = *(const ull*)(hrow + 4);
            ull h2 = *(const ull*)(hrow + 8);
            ull h3 = *(const ull*)(hrow + 12);
#pragma unroll
            for (int jj = 0; jj < 4; jj++) {
                ull ud = pack2(u_lo[jj][kq], u_lo[jj][kq]);
                acc2[jj][0] = ffma2(ud, h0, acc2[jj][0]);
                acc2[jj][1] = ffma2(ud, h1, acc2[jj][1]);
                acc2[jj][2] = ffma2(ud, h2, acc2[jj][2]);
                acc2[jj][3] = ffma2(ud, h3, acc2[jj][3]);
            }
        }

        // ---- commit half B to smem, then sync ----
#pragma unroll
        for (int it4 = 0; it4 < 4; it4++) {
            float* d = hs + kB[it4] * HSTR + pB[it4];
            *(float4*)d = sb[it4];
        }
        __syncthreads();

        // ---- compute half B: kq 8..15, u from smem ----
        const float* urow = Us + tj * 4 * USTR + ks;
#pragma unroll
        for (int kq = 0; kq < 8; kq++) {
            const float* hrow = hs + (512 + ks + 64 * kq) * HSTR + 2 * tb;
            ull h0 = *(const ull*)(hrow + 0);
            ull h1 = *(const ull*)(hrow + 4);
            ull h2 = *(const ull*)(hrow + 8);
            ull h3 = *(const ull*)(hrow + 12);
#pragma unroll
            for (int jj = 0; jj < 4; jj++) {
                float us = urow[jj * USTR + 64 * kq];
                ull ud = pack2(us, us);
                acc2[jj][0] = ffma2(ud, h0, acc2[jj][0]);
                acc2[jj][1] = ffma2(ud, h1, acc2[jj][1]);
                acc2[jj][2] = ffma2(ud, h2, acc2[jj][2]);
                acc2[jj][3] = ffma2(ud, h3, acc2[jj][3]);
            }
        }

        // ---- write partials, XOR-swizzled (2-phase-optimal STS.64) ----
#pragma unroll
        for (int jj = 0; jj < 4; jj++)
#pragma unroll
            for (int m = 0; m < 4; m++) {
                int p = (tj * 4 + jj) * 8 + 2 * m + tb;
                int col = ks ^ ((m & 1) | (tb << 1) | (tj << 2));
                red[p * 64 + col] = acc2[jj][m];
            }
        __syncthreads();

        // ---- reduce + pointwise epilogue (128 readers) ----
        if (tid < NPO) {
            ull s01 = 0ull, s23 = 0ull;
#pragma unroll
            for (int i = 0; i < 64; i += 2) {
                s01 = fadd2(s01, red[po * 64 + (i ^ sr)]);
                s23 = fadd2(s23, red[po * 64 + ((i + 1) ^ sr)]);
            }
            float2 sum = unpack2(fadd2(s01, s23));
            float2 hold = *(const float2*)(hs + jg * HSTR + 2 * bp);
            float a0 = tanhf(xwA + sum.x + biasj);
            float a1 = tanhf(xwB + sum.y + biasj);
            float h0n = decay * hold.x + DT_C * a0;
            float h1n = decay * hold.y + DT_C * a1;
            size_t off = (size_t)t * H_SZ;
            __stcg(states + sidx0 + off, h0n);
            __stcg(states + sidx1 + off, h1n);
            float2 hn = make_float2(h0n, h1n);
            __stcg((float2*)(g_hT[cur ^ 1] + (size_t)jg * B_SZ + bg0 + 2 * bp), hn);
            if (t == T_SZ - 1) {
                __stcg(hfinal + (size_t)(bg0 + 2 * bp) * H_SZ + jg, h0n);
                __stcg(hfinal + (size_t)(bg0 + 2 * bp + 1) * H_SZ + jg, h1n);
            } else {
                xwA = __ldcg(states + sidx0 + off + H_SZ);   // prefetch t+1
                xwB = __ldcg(states + sidx1 + off + H_SZ);
            }
        }
        cur ^= 1;

        // -------- software grid barrier (R1/R3-proven two-hop topology) -----
        __syncthreads();
        if (tid == 0) {
            __threadfence();
            g_arrive[blk] = t + 1;
        }
        if (blk == 0) {
            if (tid < RBLK) {
                while (g_arrive[tid] < t + 1) { }
            }
            __syncthreads();
            if (tid == 0) {
                __threadfence();
                g_release = t + 1;
            }
        }
        if (tid == 0) {
            while (g_release < t + 1) { }
            __threadfence();
        }
        __syncthreads();
    }
}

// ------------------------------------------------------------------
// Launcher
// ------------------------------------------------------------------
extern "C" void kernel_launch(void* const* d_in, const int* in_sizes, int n_in,
                              void* d_out, int out_size) {
    const float* x   = (const float*)d_in[0];   // [B, T, I]
    const float* W   = (const float*)d_in[1];   // [H, I]
    const float* U   = (const float*)d_in[2];   // [H, H]
    const float* b   = (const float*)d_in[3];   // [H]
    const float* tau = (const float*)d_in[4];   // [H]

    float* hfinal = (float*)d_out;              // [B, H]
    float* states = hfinal + B_SZ * H_SZ;       // [B, T, H]

    cudaFuncSetAttribute(recur_kernel,
                         cudaFuncAttributeMaxDynamicSharedMemorySize,
                         RECUR_SMEM);

    reset_kernel<<<32, 1024>>>();

    dim3 ggrid(H_SZ / GBN, (B_SZ * T_SZ) / GBM);
    gemm_xw<<<ggrid, 256>>>(x, W, states);

    recur_kernel<<<RBLK, 512, RECUR_SMEM>>>(states, hfinal, U, b, tau);
}